// round 1
// baseline (speedup 1.0000x reference)
#include <cuda_runtime.h>

#define NODELEN 10
#define DEG 32
#define MAXN 200000

// Scratch for hop-1 aggregated features (allocation-free rule: static __device__)
__device__ float g_h1[(size_t)MAXN * NODELEN];

// ---------------------------------------------------------------------------
// Hop kernels: one warp per node. Cooperative gather: 10 lanes read the 10
// consecutive floats of one neighbor row in a single LDG.32, 3 rows per
// instruction (lanes 0-29), minimizing L1tex wavefronts (~1.3 wf/row).
// ---------------------------------------------------------------------------

__global__ __launch_bounds__(256) void hop1_kernel(
    const float* __restrict__ features, const int* __restrict__ adj, int N)
{
    int warp = (blockIdx.x * blockDim.x + threadIdx.x) >> 5;
    int lane = threadIdx.x & 31;
    if (warp >= N) return;

    int myNb = adj[warp * DEG + lane];   // lane l holds neighbor index l (coalesced)
    int g = lane / 10;                    // subgroup 0..2 (lanes 30,31 -> g=3, idle)
    int d = lane - g * 10;                // feature dim 0..9

    float acc = 0.f;
#pragma unroll
    for (int i = 0; i < 11; i++) {
        int r = 3 * i + g;                                  // neighbor slot 0..33
        int nb = __shfl_sync(0xffffffffu, myNb, r & 31);    // broadcast owner's adj value
        if (g < 3 && r < 32)
            acc += __ldg(features + (size_t)nb * NODELEN + d);
    }
    // combine the 3 subgroup partials: lanes {d, d+10, d+20}
    float a1 = __shfl_sync(0xffffffffu, acc, lane + 10);
    float a2 = __shfl_sync(0xffffffffu, acc, lane + 20);
    if (lane < 10) {
        float v = (lane == 0) ? 0.f : (acc + a1 + a2) * (1.f / 32.f);
        g_h1[(size_t)warp * NODELEN + lane] = v;
    }
}

// Hop 2 + embedding build: agg = mean of h1 rows of neighbors (col 0 zeroed),
// emb = concat(features_n with col0 zeroed, agg). Writes emb directly to d_out.
__global__ __launch_bounds__(256) void hop2_emb_kernel(
    const float* __restrict__ features, const int* __restrict__ adj,
    float* __restrict__ emb, int N)
{
    int warp = (blockIdx.x * blockDim.x + threadIdx.x) >> 5;
    int lane = threadIdx.x & 31;
    if (warp >= N) return;

    int myNb = adj[warp * DEG + lane];
    int g = lane / 10;
    int d = lane - g * 10;

    float acc = 0.f;
#pragma unroll
    for (int i = 0; i < 11; i++) {
        int r = 3 * i + g;
        int nb = __shfl_sync(0xffffffffu, myNb, r & 31);
        if (g < 3 && r < 32)
            acc += g_h1[(size_t)nb * NODELEN + d];
    }
    float a1 = __shfl_sync(0xffffffffu, acc, lane + 10);
    float a2 = __shfl_sync(0xffffffffu, acc, lane + 20);

    float* row = emb + (size_t)warp * (2 * NODELEN);
    if (lane < 10) {
        // agg part: columns 10..19, column 10 (agg dim 0) forced to zero
        float v = (lane == 0) ? 0.f : (acc + a1 + a2) * (1.f / 32.f);
        row[10 + lane] = v;
    } else if (lane < 20) {
        // self features: columns 0..9, column 0 forced to zero
        int dd = lane - 10;
        row[dd] = (dd == 0) ? 0.f : features[(size_t)warp * NODELEN + dd];
    }
}

// ---------------------------------------------------------------------------
// MLP autoencoder: thread-per-node, all weights (1075 floats) in shared mem.
// ---------------------------------------------------------------------------
__global__ __launch_bounds__(128) void mlp_kernel(
    const float* __restrict__ emb,
    const float* __restrict__ We1, const float* __restrict__ be1,
    const float* __restrict__ We2, const float* __restrict__ be2,
    const float* __restrict__ We3, const float* __restrict__ be3,
    const float* __restrict__ Wd1, const float* __restrict__ bd1,
    const float* __restrict__ Wd2, const float* __restrict__ bd2,
    const float* __restrict__ Wd3, const float* __restrict__ bd3,
    float* __restrict__ enc_out, float* __restrict__ dec_out, int N)
{
    __shared__ float s[1075];
    {
        const float* srcs[12] = {We1, be1, We2, be2, We3, be3,
                                 Wd1, bd1, Wd2, bd2, Wd3, bd3};
        const int sz[12] = {300, 15, 150, 10, 50, 5, 50, 10, 150, 15, 300, 20};
        int off = 0;
        for (int a = 0; a < 12; a++) {
            for (int k = threadIdx.x; k < sz[a]; k += blockDim.x)
                s[off + k] = srcs[a][k];
            off += sz[a];
        }
    }
    __syncthreads();

    int n = blockIdx.x * blockDim.x + threadIdx.x;
    if (n >= N) return;

    const float* sWe1 = s;          const float* sbe1 = s + 300;
    const float* sWe2 = s + 315;    const float* sbe2 = s + 465;
    const float* sWe3 = s + 475;    const float* sbe3 = s + 525;
    const float* sWd1 = s + 530;    const float* sbd1 = s + 580;
    const float* sWd2 = s + 590;    const float* sbd2 = s + 740;
    const float* sWd3 = s + 755;    const float* sbd3 = s + 1055;

    // emb row: 20 floats, 80-byte stride => 16B aligned, use float4 loads
    float x[20];
    const float4* e4 = (const float4*)(emb + (size_t)n * 20);
#pragma unroll
    for (int i = 0; i < 5; i++) {
        float4 t = e4[i];
        x[4 * i + 0] = t.x; x[4 * i + 1] = t.y;
        x[4 * i + 2] = t.z; x[4 * i + 3] = t.w;
    }

    float h1v[15];
#pragma unroll
    for (int i = 0; i < 15; i++) {
        float a = sbe1[i];
#pragma unroll
        for (int j = 0; j < 20; j++) a = fmaf(sWe1[i * 20 + j], x[j], a);
        h1v[i] = fmaxf(a, 0.f);
    }

    float h2v[10];
#pragma unroll
    for (int i = 0; i < 10; i++) {
        float a = sbe2[i];
#pragma unroll
        for (int j = 0; j < 15; j++) a = fmaf(sWe2[i * 15 + j], h1v[j], a);
        h2v[i] = fmaxf(a, 0.f);
    }

    float ev[5];
#pragma unroll
    for (int i = 0; i < 5; i++) {
        float a = sbe3[i];
#pragma unroll
        for (int j = 0; j < 10; j++) a = fmaf(sWe3[i * 10 + j], h2v[j], a);
        ev[i] = a;  // encoded: no relu
    }
#pragma unroll
    for (int i = 0; i < 5; i++) enc_out[(size_t)n * 5 + i] = ev[i];

    float d1v[10];
#pragma unroll
    for (int i = 0; i < 10; i++) {
        float a = sbd1[i];
#pragma unroll
        for (int j = 0; j < 5; j++) a = fmaf(sWd1[i * 5 + j], ev[j], a);
        d1v[i] = fmaxf(a, 0.f);
    }

    float d2v[15];
#pragma unroll
    for (int i = 0; i < 15; i++) {
        float a = sbd2[i];
#pragma unroll
        for (int j = 0; j < 10; j++) a = fmaf(sWd2[i * 10 + j], d1v[j], a);
        d2v[i] = fmaxf(a, 0.f);
    }

    float dv[20];
#pragma unroll
    for (int i = 0; i < 20; i++) {
        float a = sbd3[i];
#pragma unroll
        for (int j = 0; j < 15; j++) a = fmaf(sWd3[i * 15 + j], d2v[j], a);
        dv[i] = a;  // decoded: no relu
    }
    float4* o4 = (float4*)(dec_out + (size_t)n * 20);
#pragma unroll
    for (int i = 0; i < 5; i++)
        o4[i] = make_float4(dv[4 * i], dv[4 * i + 1], dv[4 * i + 2], dv[4 * i + 3]);
}

// ---------------------------------------------------------------------------
extern "C" void kernel_launch(void* const* d_in, const int* in_sizes, int n_in,
                              void* d_out, int out_size)
{
    const float* features = (const float*)d_in[0];
    const int*   adj      = (const int*)d_in[1];
    const float* We1 = (const float*)d_in[2];  const float* be1 = (const float*)d_in[3];
    const float* We2 = (const float*)d_in[4];  const float* be2 = (const float*)d_in[5];
    const float* We3 = (const float*)d_in[6];  const float* be3 = (const float*)d_in[7];
    const float* Wd1 = (const float*)d_in[8];  const float* bd1 = (const float*)d_in[9];
    const float* Wd2 = (const float*)d_in[10]; const float* bd2 = (const float*)d_in[11];
    const float* Wd3 = (const float*)d_in[12]; const float* bd3 = (const float*)d_in[13];

    int N = in_sizes[0] / NODELEN;

    float* out = (float*)d_out;
    float* enc_out = out;                     // [N,5]
    float* dec_out = out + (size_t)N * 5;     // [N,20]
    float* emb_out = out + (size_t)N * 25;    // [N,20]

    // hop kernels: one warp per node, 8 warps per 256-thread block
    int hop_blocks = (N + 7) / 8;
    hop1_kernel<<<hop_blocks, 256>>>(features, adj, N);
    hop2_emb_kernel<<<hop_blocks, 256>>>(features, adj, emb_out, N);

    int mlp_blocks = (N + 127) / 128;
    mlp_kernel<<<mlp_blocks, 128>>>(emb_out,
                                    We1, be1, We2, be2, We3, be3,
                                    Wd1, bd1, Wd2, bd2, Wd3, bd3,
                                    enc_out, dec_out, N);
}